// round 17
// baseline (speedup 1.0000x reference)
#include <cuda_runtime.h>
#include <cstdint>
#include <math.h>

#define B_ 128
#define T_ 100
#define E_ 128
#define F_ 700
#define S_ 400
#define V_ 10000

// ---------------- static device scratch (no allocations allowed) ----------------
static __device__ __align__(16) float g_fh[B_ * F_];
static __device__ __align__(16) float g_fc[B_ * F_];
static __device__ __align__(16) float g_sh[B_ * S_];
static __device__ __align__(16) float g_sc[B_ * S_];
static __device__ __align__(16) float g_z[4 * B_ * 4 * F_];      // split-K planes (5.7 MB)
static __device__ __align__(16) float g_outs[B_ * T_ * F_];      // fh outputs, row = b*T + t

// pre-split (tf32 hi/lo) operand buffers — values identical to on-the-fly split
static __device__ __align__(16) float g_W0hi[(E_ + F_) * 4 * F_];
static __device__ __align__(16) float g_W0lo[(E_ + F_) * 4 * F_];
static __device__ __align__(16) float g_W1hi[(S_ + F_) * 4 * F_];
static __device__ __align__(16) float g_W1lo[(S_ + F_) * 4 * F_];
static __device__ __align__(16) float g_WShi[(F_ + S_) * 4 * S_];
static __device__ __align__(16) float g_WSlo[(F_ + S_) * 4 * S_];
static __device__ __align__(16) float g_xhi[B_ * T_ * E_];
static __device__ __align__(16) float g_xlo[B_ * T_ * E_];
static __device__ __align__(16) float g_fhhi[B_ * F_];
static __device__ __align__(16) float g_fhlo[B_ * F_];
static __device__ __align__(16) float g_shhi[B_ * S_];
static __device__ __align__(16) float g_shlo[B_ * S_];

// ---------------- helpers ----------------
__device__ __forceinline__ uint32_t f2tf32(float x) {
    uint32_t r;
    asm("cvt.rna.tf32.f32 %0, %1;" : "=r"(r) : "f"(x));
    return r;
}
__device__ __forceinline__ void f2tf32_split(float x, uint32_t& hi, uint32_t& lo) {
    hi = f2tf32(x);
    lo = f2tf32(x - __uint_as_float(hi));
}
__device__ __forceinline__ void mma_tf32(float* d, const uint32_t* a, const uint32_t* b) {
    asm volatile(
        "mma.sync.aligned.m16n8k8.row.col.f32.tf32.tf32.f32 "
        "{%0,%1,%2,%3}, {%4,%5,%6,%7}, {%8,%9}, {%0,%1,%2,%3};\n"
        : "+f"(d[0]), "+f"(d[1]), "+f"(d[2]), "+f"(d[3])
        : "r"(a[0]), "r"(a[1]), "r"(a[2]), "r"(a[3]), "r"(b[0]), "r"(b[1]));
}
__device__ __forceinline__ void cp16(void* smem, const void* gmem, int szbytes) {
    uint32_t s = (uint32_t)__cvta_generic_to_shared(smem);
    asm volatile("cp.async.cg.shared.global [%0], [%1], 16, %2;\n"
                 :: "r"(s), "l"(gmem), "r"(szbytes));
}
__device__ __forceinline__ void cp_commit() { asm volatile("cp.async.commit_group;\n"); }
template <int N> __device__ __forceinline__ void cp_wait() {
    asm volatile("cp.async.wait_group %0;\n" :: "n"(N));
}
__device__ __forceinline__ float sigm(float x) { return 1.0f / (1.0f + expf(-x)); }

// ---------------- one-shot splitter: src -> (hi, lo) tf32 pairs ----------------
__global__ void split_kernel(const float* __restrict__ src,
                             float* __restrict__ dhi, float* __restrict__ dlo, int n) {
    for (int i = blockIdx.x * blockDim.x + threadIdx.x; i < n; i += gridDim.x * blockDim.x) {
        uint32_t h, l;
        f2tf32_split(src[i], h, l);
        dhi[i] = __uint_as_float(h);
        dlo[i] = __uint_as_float(l);
    }
}

// ---------------- pre-split recurrent GEMM: zero CVT in hot loop -------------------------
// C = concat(A1,A2)[M,K] @ W[K,N], all operands pre-split (hi/lo tf32-in-fp32).
// BK=16, BM=64, BN=32, 4 warps, 2-stage cp.async, fp64 master accumulator,
// fp32 per-k-block partials. blockIdx.z = split-K index -> plane C + zb*pstride.
template <int NSPLIT>
__global__ void __launch_bounds__(128, 5)
gemm_ps_kernel(const float* __restrict__ A1h, const float* __restrict__ A1l, int lda1, int K1,
               const float* __restrict__ A2h, const float* __restrict__ A2l, int lda2,
               const float* __restrict__ Wh, const float* __restrict__ Wl,
               float* __restrict__ C, int N, int K, size_t pstride) {
    constexpr int BK = 16, BM = 64, BN = 32;
    constexpr int AST = 20;            // %32==20, tq<4 -> conflict-free frag LDS
    constexpr int BST = 40;

    __shared__ float Ah[2][BM][AST], Al[2][BM][AST];
    __shared__ float Bh[2][BK][BST], Bl[2][BK][BST];

    const int tid  = threadIdx.x;
    const int wid  = tid >> 5;
    const int lane = tid & 31;
    const int g    = lane >> 2;
    const int tq   = lane & 3;
    const int warp_m = wid & 1;
    const int warp_n = wid >> 1;
    const int m0 = blockIdx.y * BM;
    const int n0 = blockIdx.x * BN;

    const int nblk = (K + BK - 1) / BK;
    const int zb = blockIdx.z;
    const int kBegin = ((zb * nblk) / NSPLIT) * BK;
    const int kEnd   = (zb == NSPLIT - 1) ? K : (((zb + 1) * nblk) / NSPLIT) * BK;
    float* Cz = C + (size_t)zb * pstride;

    double acc[2][2][4];
#pragma unroll
    for (int mf = 0; mf < 2; ++mf)
#pragma unroll
        for (int nf = 0; nf < 2; ++nf)
#pragma unroll
            for (int r = 0; r < 4; ++r) acc[mf][nf][r] = 0.0;

    auto load_tiles = [&](int k0, int s) {
        // A: 64x16 floats = 256 float4 per (hi,lo) array; 2 iters x 128 thr
#pragma unroll
        for (int i = 0; i < 2; ++i) {
            int p   = tid + i * 128;
            int row = p >> 2;
            int kc  = (p & 3) << 2;
            int k   = k0 + kc;
            const float *sh_ = A1h, *sl_ = A1l;
            int sz = 0;
            if (k < K) {
                int gr = m0 + row;
                sz = 16;
                if (k + 4 <= K1) { sh_ = A1h + (size_t)gr * lda1 + k;        sl_ = A1l + (size_t)gr * lda1 + k; }
                else             { sh_ = A2h + (size_t)gr * lda2 + (k - K1); sl_ = A2l + (size_t)gr * lda2 + (k - K1); }
            }
            cp16(&Ah[s][row][kc], sh_, sz);
            cp16(&Al[s][row][kc], sl_, sz);
        }
        // B: 16x32 floats = 128 float4 per array; 1 iter x 128 thr
        {
            int p  = tid;
            int kr = p >> 3;
            int nc = (p & 7) << 2;
            int n  = n0 + nc;
            int k  = k0 + kr;
            const float *sh_ = Wh, *sl_ = Wl;
            int sz = 0;
            if (k < K && n < N) { sz = 16; sh_ = Wh + (size_t)k * N + n; sl_ = Wl + (size_t)k * N + n; }
            cp16(&Bh[s][kr][nc], sh_, sz);
            cp16(&Bl[s][kr][nc], sl_, sz);
        }
    };

    auto compute = [&](int s) {
        float pac[2][2][4];
#pragma unroll
        for (int mf = 0; mf < 2; ++mf)
#pragma unroll
            for (int nf = 0; nf < 2; ++nf)
#pragma unroll
                for (int r = 0; r < 4; ++r) pac[mf][nf][r] = 0.0f;

#pragma unroll
        for (int kk = 0; kk < 2; ++kk) {
            uint32_t afh[2][4], afl[2][4], bfh[2][2], bfl[2][2];
#pragma unroll
            for (int mf = 0; mf < 2; ++mf) {
                int r = warp_m * 32 + mf * 16;
                afh[mf][0] = __float_as_uint(Ah[s][r + g][kk * 8 + tq]);
                afh[mf][1] = __float_as_uint(Ah[s][r + g + 8][kk * 8 + tq]);
                afh[mf][2] = __float_as_uint(Ah[s][r + g][kk * 8 + tq + 4]);
                afh[mf][3] = __float_as_uint(Ah[s][r + g + 8][kk * 8 + tq + 4]);
                afl[mf][0] = __float_as_uint(Al[s][r + g][kk * 8 + tq]);
                afl[mf][1] = __float_as_uint(Al[s][r + g + 8][kk * 8 + tq]);
                afl[mf][2] = __float_as_uint(Al[s][r + g][kk * 8 + tq + 4]);
                afl[mf][3] = __float_as_uint(Al[s][r + g + 8][kk * 8 + tq + 4]);
            }
#pragma unroll
            for (int nf = 0; nf < 2; ++nf) {
                int cn = warp_n * 16 + nf * 8 + g;
                bfh[nf][0] = __float_as_uint(Bh[s][kk * 8 + tq][cn]);
                bfh[nf][1] = __float_as_uint(Bh[s][kk * 8 + tq + 4][cn]);
                bfl[nf][0] = __float_as_uint(Bl[s][kk * 8 + tq][cn]);
                bfl[nf][1] = __float_as_uint(Bl[s][kk * 8 + tq + 4][cn]);
            }
#pragma unroll
            for (int mf = 0; mf < 2; ++mf)
#pragma unroll
                for (int nf = 0; nf < 2; ++nf) {
                    mma_tf32(pac[mf][nf], afl[mf], bfh[nf]);
                    mma_tf32(pac[mf][nf], afh[mf], bfl[nf]);
                    mma_tf32(pac[mf][nf], afh[mf], bfh[nf]);
                }
        }
#pragma unroll
        for (int mf = 0; mf < 2; ++mf)
#pragma unroll
            for (int nf = 0; nf < 2; ++nf)
#pragma unroll
                for (int r = 0; r < 4; ++r) acc[mf][nf][r] += (double)pac[mf][nf][r];
    };

    load_tiles(kBegin, 0);
    cp_commit();
    int buf = 0;
    for (int k0 = kBegin; k0 < kEnd; k0 += BK) {
        if (k0 + BK < kEnd) load_tiles(k0 + BK, buf ^ 1);
        cp_commit();
        cp_wait<1>();
        __syncthreads();
        compute(buf);
        __syncthreads();
        buf ^= 1;
    }

#pragma unroll
    for (int mf = 0; mf < 2; ++mf)
#pragma unroll
        for (int nf = 0; nf < 2; ++nf) {
            int row = m0 + warp_m * 32 + mf * 16 + g;
            int col = n0 + warp_n * 16 + nf * 8 + tq * 2;
            if (col < N) {
                float2 v0 = make_float2((float)acc[mf][nf][0], (float)acc[mf][nf][1]);
                float2 v1 = make_float2((float)acc[mf][nf][2], (float)acc[mf][nf][3]);
                *(float2*)(Cz + (size_t)row * N + col)       = v0;
                *(float2*)(Cz + (size_t)(row + 8) * N + col) = v1;
            }
        }
}

// ---------------- generic TF32 GEMM (output projection only; unchanged from R16) ---------
template <int BM, int BN, int WM_, int WN_, int STAGES, int MINCTA>
__global__ void __launch_bounds__(WM_ * WN_ * 32, MINCTA)
gemm_out_kernel(const float* __restrict__ A, int lda,
                const float* __restrict__ W, const float* __restrict__ bias,
                float* __restrict__ C, int N, int K) {
    constexpr int BK = 32;
    constexpr int NTH = WM_ * WN_ * 32;
    constexpr int WTM = BM / WM_;
    constexpr int WTN = BN / WN_;
    constexpr int MF = WTM / 16;
    constexpr int NF = WTN / 8;
    constexpr int AST = BK + 4;
    constexpr int BST = BN + 8;

    __shared__ float As[STAGES][BM][AST];
    __shared__ float Bs[STAGES][BK][BST];

    const int tid  = threadIdx.x;
    const int wid  = tid >> 5;
    const int lane = tid & 31;
    const int g    = lane >> 2;
    const int tq   = lane & 3;
    const int warp_m = wid % WM_;
    const int warp_n = wid / WM_;
    const int m0 = blockIdx.y * BM;
    const int n0 = blockIdx.x * BN;

    float acc[MF][NF][4];
#pragma unroll
    for (int mf = 0; mf < MF; ++mf)
#pragma unroll
        for (int nf = 0; nf < NF; ++nf)
#pragma unroll
            for (int r = 0; r < 4; ++r) acc[mf][nf][r] = 0.0f;

    auto load_tiles = [&](int k0, int s) {
        constexpr int AF4 = BM * BK / 4;
#pragma unroll
        for (int i = 0; i < AF4 / NTH; ++i) {
            int p   = tid + i * NTH;
            int row = p >> 3;
            int kc  = (p & 7) << 2;
            int k   = k0 + kc;
            const float* src = A;
            int sz = 0;
            if (k < K) { sz = 16; src = A + (size_t)(m0 + row) * lda + k; }
            cp16(&As[s][row][kc], src, sz);
        }
        constexpr int BF4 = BK * BN / 4;
#pragma unroll
        for (int i = 0; i < BF4 / NTH; ++i) {
            int p  = tid + i * NTH;
            int kr = p / (BN / 4);
            int nc = (p % (BN / 4)) << 2;
            int n  = n0 + nc;
            int k  = k0 + kr;
            const float* src = W;
            int sz = 0;
            if (k < K && n < N) { sz = 16; src = W + (size_t)k * N + n; }
            cp16(&Bs[s][kr][nc], src, sz);
        }
    };

    auto compute = [&](int s) {
#pragma unroll
        for (int kk = 0; kk < 4; ++kk) {
            uint32_t af[MF][4], bf[NF][2];
#pragma unroll
            for (int mf = 0; mf < MF; ++mf) {
                int r = warp_m * WTM + mf * 16;
                af[mf][0] = f2tf32(As[s][r + g][kk * 8 + tq]);
                af[mf][1] = f2tf32(As[s][r + g + 8][kk * 8 + tq]);
                af[mf][2] = f2tf32(As[s][r + g][kk * 8 + tq + 4]);
                af[mf][3] = f2tf32(As[s][r + g + 8][kk * 8 + tq + 4]);
            }
#pragma unroll
            for (int nf = 0; nf < NF; ++nf) {
                int cn = warp_n * WTN + nf * 8 + g;
                bf[nf][0] = f2tf32(Bs[s][kk * 8 + tq][cn]);
                bf[nf][1] = f2tf32(Bs[s][kk * 8 + tq + 4][cn]);
            }
#pragma unroll
            for (int mf = 0; mf < MF; ++mf)
#pragma unroll
                for (int nf = 0; nf < NF; ++nf) mma_tf32(acc[mf][nf], af[mf], bf[nf]);
        }
    };

    load_tiles(0, 0);
    cp_commit();
    int buf = 0;
    for (int k0 = 0; k0 < K; k0 += BK) {
        if (k0 + BK < K) load_tiles(k0 + BK, buf ^ 1);
        cp_commit();
        cp_wait<1>();
        __syncthreads();
        compute(buf);
        __syncthreads();
        buf ^= 1;
    }

#pragma unroll
    for (int mf = 0; mf < MF; ++mf) {
#pragma unroll
        for (int nf = 0; nf < NF; ++nf) {
            int row = m0 + warp_m * WTM + mf * 16 + g;
            int col = n0 + warp_n * WTN + nf * 8 + tq * 2;
            if (col < N) {
                float bx = bias[col], by = bias[col + 1];
                float2 v0 = make_float2(acc[mf][nf][0] + bx, acc[mf][nf][1] + by);
                float2 v1 = make_float2(acc[mf][nf][2] + bx, acc[mf][nf][3] + by);
                *(float2*)(C + (size_t)row * N + col)       = v0;
                *(float2*)(C + (size_t)(row + 8) * N + col) = v1;
            }
        }
    }
}

// ---------------- fused split-K reduce + LN4 + gates + LN(c) + zoneout --------------------
// Also emits tf32 hi/lo split of the new h (consumed by the pre-split GEMMs).
template <int HU, int NS>
__global__ void __launch_bounds__(256)
pointwise_kernel(const float* __restrict__ z, size_t pstride,
                 const float* __restrict__ bias,
                 const float* __restrict__ gg, const float* __restrict__ bg,
                 const float* __restrict__ gc, const float* __restrict__ bc,
                 float* __restrict__ h, float* __restrict__ c,
                 float* __restrict__ hhi, float* __restrict__ hlo,
                 float* __restrict__ outs) {
    constexpr int NTH = 256;
    __shared__ float sz[4 * HU];
    __shared__ float scp[HU];
    __shared__ double redd[16];
    __shared__ float stat[10];

    const int b = blockIdx.x, tid = threadIdx.x;
    const float* zr = z + (size_t)b * 4 * HU;

    for (int i = tid; i < 4 * HU; i += NTH) {
        float v = zr[i];
#pragma unroll
        for (int s = 1; s < NS; ++s) v += zr[s * pstride + i];
        sz[i] = v + bias[i];
    }
    __syncthreads();

    for (int ch = 0; ch < 4; ++ch) {
        double s = 0.0, q = 0.0;
        for (int i = tid; i < HU; i += NTH) {
            double v = (double)sz[ch * HU + i];
            s += v; q += v * v;
        }
#pragma unroll
        for (int o = 16; o; o >>= 1) { s += __shfl_xor_sync(~0u, s, o); q += __shfl_xor_sync(~0u, q, o); }
        if ((tid & 31) == 0) { redd[tid >> 5] = s; redd[8 + (tid >> 5)] = q; }
        __syncthreads();
        if (tid < 32) {
            double ss = (tid < 8) ? redd[tid] : 0.0;
            double qq = (tid < 8) ? redd[8 + tid] : 0.0;
#pragma unroll
            for (int o = 4; o; o >>= 1) { ss += __shfl_xor_sync(~0u, ss, o); qq += __shfl_xor_sync(~0u, qq, o); }
            if (tid == 0) {
                double mu = ss / (double)HU;
                double var = qq / (double)HU - mu * mu;
                stat[ch] = (float)mu;
                stat[4 + ch] = (float)(1.0 / sqrt(var + 1e-5));
            }
        }
        __syncthreads();
    }

    const float mu0 = stat[0], mu1 = stat[1], mu2 = stat[2], mu3 = stat[3];
    const float r0 = stat[4], r1 = stat[5], r2 = stat[6], r3 = stat[7];

    for (int i = tid; i < HU; i += NTH) {
        float iv = (sz[i]          - mu0) * r0 * gg[i]          + bg[i];
        float jv = (sz[HU + i]     - mu1) * r1 * gg[HU + i]     + bg[HU + i];
        float fv = (sz[2 * HU + i] - mu2) * r2 * gg[2 * HU + i] + bg[2 * HU + i];
        float ov = (sz[3 * HU + i] - mu3) * r3 * gg[3 * HU + i] + bg[3 * HU + i];
        float cold = c[(size_t)b * HU + i];
        float cpre = cold * sigm(fv + 1.0f) + sigm(iv) * tanhf(jv);
        scp[i] = cpre;
        sz[3 * HU + i] = ov;
    }
    __syncthreads();

    {
        double s = 0.0, q = 0.0;
        for (int i = tid; i < HU; i += NTH) {
            double v = (double)scp[i];
            s += v; q += v * v;
        }
#pragma unroll
        for (int o = 16; o; o >>= 1) { s += __shfl_xor_sync(~0u, s, o); q += __shfl_xor_sync(~0u, q, o); }
        if ((tid & 31) == 0) { redd[tid >> 5] = s; redd[8 + (tid >> 5)] = q; }
        __syncthreads();
        if (tid < 32) {
            double ss = (tid < 8) ? redd[tid] : 0.0;
            double qq = (tid < 8) ? redd[8 + tid] : 0.0;
#pragma unroll
            for (int o = 4; o; o >>= 1) { ss += __shfl_xor_sync(~0u, ss, o); qq += __shfl_xor_sync(~0u, qq, o); }
            if (tid == 0) {
                double mu = ss / (double)HU;
                double var = qq / (double)HU - mu * mu;
                stat[8] = (float)mu;
                stat[9] = (float)(1.0 / sqrt(var + 1e-5));
            }
        }
        __syncthreads();
    }
    const float muc = stat[8], rc = stat[9];

    for (int i = tid; i < HU; i += NTH) {
        float cpre = scp[i];
        float nh = tanhf((cpre - muc) * rc * gc[i] + bc[i]) * sigm(sz[3 * HU + i]);
        float hold = h[(size_t)b * HU + i];
        float cold = c[(size_t)b * HU + i];
        float hn = 0.9f * nh + 0.1f * hold;
        float cn = 0.5f * cpre + 0.5f * cold;
        h[(size_t)b * HU + i] = hn;
        c[(size_t)b * HU + i] = cn;
        uint32_t sh_, sl_;
        f2tf32_split(hn, sh_, sl_);
        hhi[(size_t)b * HU + i] = __uint_as_float(sh_);
        hlo[(size_t)b * HU + i] = __uint_as_float(sl_);
        if (outs) outs[(size_t)b * T_ * HU + i] = hn;
    }
}

// ---------------- init & epilogue ----------------
__global__ void zero_states_kernel() {
    int i = blockIdx.x * blockDim.x + threadIdx.x;
    if (i < B_ * F_) {
        g_fh[i] = 0.f; g_fc[i] = 0.f; g_fhhi[i] = 0.f; g_fhlo[i] = 0.f;
    }
    if (i < B_ * S_) {
        g_sh[i] = 0.f; g_sc[i] = 0.f; g_shhi[i] = 0.f; g_shlo[i] = 0.f;
    }
}

__global__ void copy_states_kernel(float* __restrict__ out) {
    int i = blockIdx.x * blockDim.x + threadIdx.x;
    const int NF = B_ * F_;
    const int NS = B_ * S_;
    if (i < NF)                       out[i] = g_fh[i];
    else if (i < 2 * NF)              out[i] = g_fc[i - NF];
    else if (i < 2 * NF + NS)         out[i] = g_sh[i - 2 * NF];
    else if (i < 2 * NF + 2 * NS)     out[i] = g_sc[i - 2 * NF - NS];
}

// ---------------- launch ----------------
extern "C" void kernel_launch(void* const* d_in, const int* in_sizes, int n_in,
                              void* d_out, int out_size) {
    const float* inputs = (const float*)d_in[0];
    const float* W0  = (const float*)d_in[1];
    const float* b0  = (const float*)d_in[2];
    const float* g0  = (const float*)d_in[3];
    const float* bg0 = (const float*)d_in[4];
    const float* gc0 = (const float*)d_in[5];
    const float* bc0 = (const float*)d_in[6];
    const float* W1  = (const float*)d_in[7];
    const float* b1  = (const float*)d_in[8];
    const float* g1  = (const float*)d_in[9];
    const float* bg1 = (const float*)d_in[10];
    const float* gc1 = (const float*)d_in[11];
    const float* bc1 = (const float*)d_in[12];
    const float* WS  = (const float*)d_in[13];
    const float* bS  = (const float*)d_in[14];
    const float* gS  = (const float*)d_in[15];
    const float* bgS = (const float*)d_in[16];
    const float* gcS = (const float*)d_in[17];
    const float* bcS = (const float*)d_in[18];
    const float* Wout = (const float*)d_in[19];
    const float* bout = (const float*)d_in[20];
    float* out = (float*)d_out;

    float *fh, *fc, *sh, *sc, *z, *outs;
    float *W0hi, *W0lo, *W1hi, *W1lo, *WShi, *WSlo, *xhi, *xlo, *fhhi, *fhlo, *shhi, *shlo;
    cudaGetSymbolAddress((void**)&fh, g_fh);
    cudaGetSymbolAddress((void**)&fc, g_fc);
    cudaGetSymbolAddress((void**)&sh, g_sh);
    cudaGetSymbolAddress((void**)&sc, g_sc);
    cudaGetSymbolAddress((void**)&z, g_z);
    cudaGetSymbolAddress((void**)&outs, g_outs);
    cudaGetSymbolAddress((void**)&W0hi, g_W0hi);
    cudaGetSymbolAddress((void**)&W0lo, g_W0lo);
    cudaGetSymbolAddress((void**)&W1hi, g_W1hi);
    cudaGetSymbolAddress((void**)&W1lo, g_W1lo);
    cudaGetSymbolAddress((void**)&WShi, g_WShi);
    cudaGetSymbolAddress((void**)&WSlo, g_WSlo);
    cudaGetSymbolAddress((void**)&xhi, g_xhi);
    cudaGetSymbolAddress((void**)&xlo, g_xlo);
    cudaGetSymbolAddress((void**)&fhhi, g_fhhi);
    cudaGetSymbolAddress((void**)&fhlo, g_fhlo);
    cudaGetSymbolAddress((void**)&shhi, g_shhi);
    cudaGetSymbolAddress((void**)&shlo, g_shlo);

    const size_t psF = (size_t)B_ * 4 * F_;
    const size_t psS = (size_t)B_ * 4 * S_;

    zero_states_kernel<<<350, 256>>>();
    split_kernel<<<592, 256>>>(W0, W0hi, W0lo, (E_ + F_) * 4 * F_);
    split_kernel<<<592, 256>>>(W1, W1hi, W1lo, (S_ + F_) * 4 * F_);
    split_kernel<<<592, 256>>>(WS, WShi, WSlo, (F_ + S_) * 4 * S_);
    split_kernel<<<592, 256>>>(inputs, xhi, xlo, B_ * T_ * E_);

    for (int t = 0; t < T_; ++t) {
        // Fast cell 0: concat(x_t, fh) @ W0 -> 4 planes (704 CTAs, 1 wave @5/SM)
        gemm_ps_kernel<4><<<dim3(88, 2, 4), 128>>>(
            xhi + (size_t)t * E_, xlo + (size_t)t * E_, T_ * E_, E_,
            fhhi, fhlo, F_, W0hi, W0lo, z, 4 * F_, E_ + F_, psF);
        pointwise_kernel<F_, 4><<<B_, 256>>>(z, psF, b0, g0, bg0, gc0, bc0,
                                             fh, fc, fhhi, fhlo, nullptr);

        // Slow cell: concat(fh, sh) @ WS -> 7 planes (700 CTAs, 1 wave @5/SM)
        gemm_ps_kernel<7><<<dim3(50, 2, 7), 128>>>(
            fhhi, fhlo, F_, F_, shhi, shlo, S_, WShi, WSlo, z, 4 * S_, F_ + S_, psS);
        pointwise_kernel<S_, 7><<<B_, 256>>>(z, psS, bS, gS, bgS, gcS, bcS,
                                             sh, sc, shhi, shlo, nullptr);

        // Fast cell 1: concat(sh, fh) @ W1 -> 4 planes
        gemm_ps_kernel<4><<<dim3(88, 2, 4), 128>>>(
            shhi, shlo, S_, S_, fhhi, fhlo, F_, W1hi, W1lo, z, 4 * F_, S_ + F_, psF);
        pointwise_kernel<F_, 4><<<B_, 256>>>(z, psF, b1, g1, bg1, gc1, bc1,
                                             fh, fc, fhhi, fhlo, outs + (size_t)t * F_);
    }

    // Output projection (R16 config, bit-identical logits)
    gemm_out_kernel<64, 64, 2, 2, 2, 5><<<dim3(157, 200), 128>>>(
        outs, F_, Wout, bout, out, V_, F_);

    copy_states_kernel<<<1100, 256>>>(out + (size_t)B_ * T_ * V_);
}